// round 1
// baseline (speedup 1.0000x reference)
#include <cuda_runtime.h>

#define HH 256
#define WW 256
#define BB 2
#define CC 64
#define EPSV 1e-5f
#define NPIX (HH*WW)
#define NGRP 16                      // B * groups = 2*8
#define NELEM_GRP (8*NPIX*2)         // 8 channels * H*W * 2 cosets

// ---------------- scratch (device globals: allowed) ----------------
__device__ float g_t[2][BB][CC][HH][WW];   // conv1 output (pre-gn2), [coset][b][c][h][w]
__device__ float g_s[2][BB][CC][HH][WW];   // skip 1x1 output (pre-gn)
__device__ float g_sum_x[NGRP], g_ssq_x[NGRP];
__device__ float g_sum_t[NGRP], g_ssq_t[NGRP];
__device__ float g_sum_s[NGRP], g_ssq_s[NGRP];
__device__ float g_mean1[NGRP], g_inv1[NGRP];
__device__ float g_mean2[NGRP], g_inv2[NGRP];
__device__ float g_means[NGRP], g_invs[NGRP];

// ---------------- small kernels ----------------
__global__ void zero_stats_k() {
    int i = threadIdx.x;
    if (i < NGRP) {
        g_sum_x[i] = 0.f; g_ssq_x[i] = 0.f;
        g_sum_t[i] = 0.f; g_ssq_t[i] = 0.f;
        g_sum_s[i] = 0.f; g_ssq_s[i] = 0.f;
    }
}

__global__ void stats_x_k(const float* __restrict__ x0, const float* __restrict__ x1) {
    int slab = blockIdx.y;                     // cs*16 + b*8 + g
    int cs = slab >> 4, b = (slab >> 3) & 1, g = slab & 7;
    const float* src = (cs ? x1 : x0) + ((size_t)(b*CC + g*8)) * NPIX
                       + (size_t)blockIdx.x * 16384;
    const float4* p = (const float4*)src;
    float s = 0.f, ss = 0.f;
    for (int i = threadIdx.x; i < 4096; i += 256) {
        float4 v = p[i];
        s  += (v.x + v.y) + (v.z + v.w);
        ss += (v.x*v.x + v.y*v.y) + (v.z*v.z + v.w*v.w);
    }
    __shared__ float sh[256], sh2[256];
    sh[threadIdx.x] = s; sh2[threadIdx.x] = ss;
    __syncthreads();
    for (int o = 128; o > 0; o >>= 1) {
        if (threadIdx.x < o) { sh[threadIdx.x] += sh[threadIdx.x+o]; sh2[threadIdx.x] += sh2[threadIdx.x+o]; }
        __syncthreads();
    }
    if (threadIdx.x == 0) {
        atomicAdd(&g_sum_x[b*8+g], sh[0]);
        atomicAdd(&g_ssq_x[b*8+g], sh2[0]);
    }
}

__global__ void finalize1_k() {
    int i = threadIdx.x;
    if (i < NGRP) {
        float n = (float)NELEM_GRP;
        float m = g_sum_x[i] / n;
        float v = g_ssq_x[i] / n - m*m;
        g_mean1[i] = m; g_inv1[i] = rsqrtf(v + EPSV);
    }
}

__global__ void finalize2_k() {
    int i = threadIdx.x;
    float n = (float)NELEM_GRP;
    if (i < NGRP) {
        float m = g_sum_t[i] / n;
        float v = g_ssq_t[i] / n - m*m;
        g_mean2[i] = m; g_inv2[i] = rsqrtf(v + EPSV);
    } else if (i < 2*NGRP) {
        int j = i - NGRP;
        float m = g_sum_s[j] / n;
        float v = g_ssq_s[j] / n - m*m;
        g_means[j] = m; g_invs[j] = rsqrtf(v + EPSV);
    }
}

// ---------------- fused conv kernel ----------------
// Tile: TH x TW pixels, all 64 output channels, one (batch, coset) per block z.
// 512 threads = 16 warps; warp w owns output channels [4w, 4w+4);
// lane l owns pixel-group: row r = l>>2 (0..7), cols cb..cb+3 with cb = 4*(l&3).
//
// out_c[o,y,x] = sum_i Wc[o,i]*hsame[i,y,x]
//             + sum_i sum_{kh,kw} Wk[o,i,kh,kw]*hcross[i, y+kh-1+c, x+kw-1+c]  (+bias)
#define TH 8
#define TW 16
#define NT 512

template<int PASS>
__global__ __launch_bounds__(NT, 1)
void conv_qc_k(const float* __restrict__ in0, const float* __restrict__ in1,
               const float* __restrict__ Wc, const float* __restrict__ Wk,
               const float* __restrict__ Bi,
               const float* __restrict__ Ga, const float* __restrict__ Be,
               const float* __restrict__ Ws, const float* __restrict__ Bs,
               const float* __restrict__ Gs, const float* __restrict__ BeS,
               float* __restrict__ Out)
{
    extern __shared__ float sm[];
    float* sWc = sm;                                  // 4096
    float* sWk = sm + 4096;                           // 16384  ((o*64+i)*4 + tap)
    float* sWs = sm + 20480;                          // 4096 (PASS1 only)
    const int wsz = (PASS == 1) ? 4096 : 0;
    float* sScale = sm + 20480 + wsz;                 // 64
    float* sShift = sScale + CC;                      // 64
    float* sSame  = sShift + CC;                      // [16][8][16]  = 2048 (raw)
    float* sCross = sSame + 2048;                     // [16][9][20] = 2880 (normalized+relu)

    int tid  = threadIdx.x;
    int warp = tid >> 5, lane = tid & 31;
    int ocb  = warp * 4;
    int r    = lane >> 2, cb = (lane & 3) * 4;
    int z = blockIdx.z; int b = z & 1, cs = z >> 1;
    int y0 = blockIdx.y * TH, xb = blockIdx.x * TW;

    const float* same_base;
    const float* cross_base;
    if (PASS == 1) {
        same_base  = (cs ? in1 : in0) + (size_t)b * CC * NPIX;
        cross_base = (cs ? in0 : in1) + (size_t)b * CC * NPIX;
    } else {
        same_base  = &g_t[cs][b][0][0][0];
        cross_base = &g_t[cs ^ 1][b][0][0][0];
    }
    const float* meanA = (PASS == 1) ? g_mean1 : g_mean2;
    const float* invA  = (PASS == 1) ? g_inv1  : g_inv2;

    // weights -> smem (contiguous copies)
    for (int i = tid; i < 1024; i += NT) ((float4*)sWc)[i] = ((const float4*)Wc)[i];
    for (int i = tid; i < 4096; i += NT) ((float4*)sWk)[i] = ((const float4*)Wk)[i];
    if (PASS == 1)
        for (int i = tid; i < 1024; i += NT) ((float4*)sWs)[i] = ((const float4*)Ws)[i];
    if (tid < CC) {
        int grp = tid >> 3;
        float m = meanA[b*8+grp], iv = invA[b*8+grp];
        float sc = iv * Ga[tid];
        sScale[tid] = sc;
        sShift[tid] = Be[tid] - m * sc;
    }

    float acc[4][4];
    float accs[4][4];
    #pragma unroll
    for (int o = 0; o < 4; ++o) {
        float bv = Bi[ocb+o];
        float bs = (PASS == 1) ? Bs[ocb+o] : 0.f;
        #pragma unroll
        for (int p = 0; p < 4; ++p) { acc[o][p] = bv; accs[o][p] = bs; }
    }

    for (int icc = 0; icc < 4; ++icc) {
        __syncthreads();
        // same-coset tile (raw; normalized at use so PASS1 skip sees raw x)
        {
            int ic = tid >> 5, q = tid & 31;
            int row = q >> 2, c4 = (q & 3) * 4;
            const float* src = same_base + (size_t)(icc*16+ic)*NPIX
                               + (size_t)(y0+row)*WW + xb + c4;
            *(float4*)&sSame[ic*128 + row*16 + c4] = *(const float4*)src;
        }
        // cross-coset tile with halo: origin (y0+cs-1, xb+cs-1), 9x17 used, stride 20
        for (int idx = tid; idx < 16*9*17; idx += NT) {
            int ic = idx / 153, rem = idx % 153;
            int row = rem / 17, col = rem % 17;
            int gy = y0 + cs - 1 + row;
            int gx = xb + cs - 1 + col;
            int gic = icc*16 + ic;
            float v = 0.f;
            if ((unsigned)gy < HH && (unsigned)gx < WW) {
                float raw = cross_base[(size_t)gic*NPIX + (size_t)gy*WW + gx];
                v = fmaxf(fmaf(raw, sScale[gic], sShift[gic]), 0.f);
            }
            sCross[ic*180 + row*20 + col] = v;
        }
        __syncthreads();

        #pragma unroll 8
        for (int ic = 0; ic < 16; ++ic) {
            int gic = icc*16 + ic;
            float sc = sScale[gic], sf = sShift[gic];
            float4 rv = *(float4*)&sSame[ic*128 + r*16 + cb];
            float hh[4] = { fmaxf(fmaf(rv.x, sc, sf), 0.f),
                            fmaxf(fmaf(rv.y, sc, sf), 0.f),
                            fmaxf(fmaf(rv.z, sc, sf), 0.f),
                            fmaxf(fmaf(rv.w, sc, sf), 0.f) };
            float rw[4] = { rv.x, rv.y, rv.z, rv.w };
            const float* crp = &sCross[ic*180 + r*20 + cb];
            float4 c0a = *(const float4*)crp;        float c04 = crp[4];
            float4 c1a = *(const float4*)(crp + 20); float c14 = crp[24];
            float c0[5] = { c0a.x, c0a.y, c0a.z, c0a.w, c04 };
            float c1[5] = { c1a.x, c1a.y, c1a.z, c1a.w, c14 };
            #pragma unroll
            for (int o = 0; o < 4; ++o) {
                int oi = (ocb + o) * 64 + gic;
                float wcv  = sWc[oi];
                float4 wkv = *(float4*)&sWk[oi*4];
                float wsv = (PASS == 1) ? sWs[oi] : 0.f;
                #pragma unroll
                for (int p = 0; p < 4; ++p) {
                    float a = acc[o][p];
                    a = fmaf(wcv,   hh[p],   a);
                    a = fmaf(wkv.x, c0[p],   a);
                    a = fmaf(wkv.y, c0[p+1], a);
                    a = fmaf(wkv.z, c1[p],   a);
                    a = fmaf(wkv.w, c1[p+1], a);
                    acc[o][p] = a;
                    if (PASS == 1) accs[o][p] = fmaf(wsv, rw[p], accs[o][p]);
                }
            }
        }
    }

    size_t pixoff = (size_t)(y0 + r) * WW + xb + cb;
    if (PASS == 1) {
        float st = 0.f, sst = 0.f, sv = 0.f, ssv = 0.f;
        #pragma unroll
        for (int o = 0; o < 4; ++o) {
            int oc = ocb + o;
            float* tp = &g_t[cs][b][oc][0][0] + pixoff;
            float* sp = &g_s[cs][b][oc][0][0] + pixoff;
            *(float4*)tp = make_float4(acc[o][0], acc[o][1], acc[o][2], acc[o][3]);
            *(float4*)sp = make_float4(accs[o][0], accs[o][1], accs[o][2], accs[o][3]);
            #pragma unroll
            for (int p = 0; p < 4; ++p) {
                st += acc[o][p];  sst += acc[o][p]  * acc[o][p];
                sv += accs[o][p]; ssv += accs[o][p] * accs[o][p];
            }
        }
        #pragma unroll
        for (int off = 16; off; off >>= 1) {
            st  += __shfl_xor_sync(0xffffffffu, st,  off);
            sst += __shfl_xor_sync(0xffffffffu, sst, off);
            sv  += __shfl_xor_sync(0xffffffffu, sv,  off);
            ssv += __shfl_xor_sync(0xffffffffu, ssv, off);
        }
        if (lane == 0) {
            int gi = b*8 + (ocb >> 3);
            atomicAdd(&g_sum_t[gi], st); atomicAdd(&g_ssq_t[gi], sst);
            atomicAdd(&g_sum_s[gi], sv); atomicAdd(&g_ssq_s[gi], ssv);
        }
    } else {
        #pragma unroll
        for (int o = 0; o < 4; ++o) {
            int oc = ocb + o;
            int gi = b*8 + (oc >> 3);
            float iv  = g_invs[gi];
            float gsc = Gs[oc] * iv;
            float gsh = BeS[oc] - g_means[gi] * gsc;
            const float* sp = &g_s[cs][b][oc][0][0] + pixoff;
            float4 sv4 = *(const float4*)sp;
            float4 ov;
            ov.x = acc[o][0] + fmaf(sv4.x, gsc, gsh);
            ov.y = acc[o][1] + fmaf(sv4.y, gsc, gsh);
            ov.z = acc[o][2] + fmaf(sv4.z, gsc, gsh);
            ov.w = acc[o][3] + fmaf(sv4.w, gsc, gsh);
            float* op = Out + (((size_t)cs*BB + b)*CC + oc)*NPIX + pixoff;
            *(float4*)op = ov;
        }
    }
}

// ---------------- launch ----------------
extern "C" void kernel_launch(void* const* d_in, const int* in_sizes, int n_in,
                              void* d_out, int out_size) {
    const float* x0      = (const float*)d_in[0];
    const float* x1      = (const float*)d_in[1];
    const float* g1      = (const float*)d_in[2];
    const float* b1      = (const float*)d_in[3];
    const float* w1c     = (const float*)d_in[4];
    const float* w1k     = (const float*)d_in[5];
    const float* bias1   = (const float*)d_in[6];
    const float* g2      = (const float*)d_in[7];
    const float* b2      = (const float*)d_in[8];
    const float* w2c     = (const float*)d_in[9];
    const float* w2k     = (const float*)d_in[10];
    const float* bias2   = (const float*)d_in[11];
    const float* wskip   = (const float*)d_in[12];
    const float* bskip   = (const float*)d_in[13];
    const float* gskip   = (const float*)d_in[14];
    const float* betask  = (const float*)d_in[15];

    const int SMEM1 = (20480 + 4096 + 64 + 64 + 2048 + 2880) * 4;  // 118528 B
    const int SMEM2 = (20480 +        64 + 64 + 2048 + 2880) * 4;  // 102144 B
    cudaFuncSetAttribute(conv_qc_k<1>, cudaFuncAttributeMaxDynamicSharedMemorySize, SMEM1);
    cudaFuncSetAttribute(conv_qc_k<2>, cudaFuncAttributeMaxDynamicSharedMemorySize, SMEM2);

    zero_stats_k<<<1, 128>>>();
    stats_x_k<<<dim3(32, 32), 256>>>(x0, x1);
    finalize1_k<<<1, 32>>>();

    dim3 grid(WW/TW, HH/TH, 4);   // (16, 32, 4): z = b + 2*coset
    conv_qc_k<1><<<grid, NT, SMEM1>>>(x0, x1, w1c, w1k, bias1, g1, b1,
                                      wskip, bskip, nullptr, nullptr, nullptr);
    finalize2_k<<<1, 64>>>();
    conv_qc_k<2><<<grid, NT, SMEM2>>>(nullptr, nullptr, w2c, w2k, bias2, g2, b2,
                                      nullptr, nullptr, gskip, betask, (float*)d_out);
    (void)in_sizes; (void)n_in; (void)out_size;
}